// round 2
// baseline (speedup 1.0000x reference)
#include <cuda_runtime.h>
#include <cuda_bf16.h>

// Problem constants (fixed by the dataset): N=150000 nodes, E=1e6 edges, D=64.
#define NMAX   150016
#define EMAX   1000448
#define DIM    64

// Scratch (no allocations allowed -> __device__ globals).
__device__ float g_Z[NMAX * DIM];     // emb @ W[l]
__device__ float g_bufA[NMAX * DIM];  // layer output ping
__device__ float g_bufB[NMAX * DIM];  // layer output pong
__device__ float g_acc[NMAX * DIM];   // sum of layer outputs
__device__ float g_s[EMAX];           // per-edge score / exp
__device__ float g_m[NMAX];           // segment max (by src)
__device__ float g_den[NMAX];         // segment sum of exp (by src)

// ---- buffer selectors (avoid cudaGetSymbolAddress during capture) ----
__device__ __forceinline__ const float* sel_cur(int sel, const float* emb_in) {
    if (sel == 0) return emb_in;
    return (sel == 1) ? g_bufA : g_bufB;
}
__device__ __forceinline__ float* sel_next(int sel) {
    return (sel == 1) ? g_bufA : g_bufB;
}

__device__ __forceinline__ void atomicMaxFloat(float* addr, float val) {
    if (val >= 0.0f) {
        atomicMax((int*)addr, __float_as_int(val));
    } else {
        atomicMin((unsigned int*)addr, __float_as_uint(val));
    }
}

// Zero the accumulator (once per launch, keeps replays deterministic).
__global__ void k_zero_acc(int nd) {
    int i = blockIdx.x * blockDim.x + threadIdx.x;
    if (i < nd) g_acc[i] = 0.0f;
}

// Per-layer init: zero next buffer, denom; m = -inf.
__global__ void k_layer_init(int nextSel, int N) {
    int i = blockIdx.x * blockDim.x + threadIdx.x;
    float* next = sel_next(nextSel);
    if (i < N * DIM) next[i] = 0.0f;
    if (i < N) {
        g_m[i]   = __int_as_float(0xff800000);  // -inf
        g_den[i] = 0.0f;
    }
}

// Z = cur @ W   (N x 64) @ (64 x 64). 4 rows per 256-thread block.
__global__ void k_gemm64(int curSel, const float* __restrict__ emb_in,
                         const float* __restrict__ W, int N) {
    __shared__ float sW[DIM * DIM];   // 16 KB
    __shared__ float sX[4 * DIM];
    const float* X = sel_cur(curSel, emb_in);
    int tid = threadIdx.x;
    #pragma unroll
    for (int i = tid; i < DIM * DIM; i += 256) sW[i] = W[i];
    int r = tid >> 6;          // 0..3
    int c = tid & 63;          // 0..63
    int row = blockIdx.x * 4 + r;
    sX[tid] = (row < N) ? X[row * DIM + c] : 0.0f;
    __syncthreads();
    float acc = 0.0f;
    #pragma unroll
    for (int k = 0; k < DIM; k++)
        acc = fmaf(sX[r * DIM + k], sW[k * DIM + c], acc);
    if (row < N) g_Z[row * DIM + c] = acc;
}

// Edge scores: warp per edge. s = dot(Z[dst], cur[src]) + 64*exp(scale*ea) + bias,
// leaky_relu(0.2), then atomicMax into g_m[src].
__global__ void k_score(const int* __restrict__ ei, const float* __restrict__ ea,
                        int curSel, const float* __restrict__ emb_in,
                        const float* __restrict__ bias_p, const float* __restrict__ scale_p,
                        int E, int layer) {
    int warp = (blockIdx.x * blockDim.x + threadIdx.x) >> 5;
    int lane = threadIdx.x & 31;
    if (warp >= E) return;
    const float* cur = sel_cur(curSel, emb_in);
    int src = ei[warp];
    int dst = ei[E + warp];
    const float2* zp = (const float2*)(g_Z + (size_t)dst * DIM);
    const float2* xp = (const float2*)(cur + (size_t)src * DIM);
    float2 z = zp[lane];
    float2 x = xp[lane];
    float p = fmaf(z.x, x.x, z.y * x.y);
    #pragma unroll
    for (int o = 16; o; o >>= 1) p += __shfl_xor_sync(0xffffffffu, p, o);
    if (lane == 0) {
        float s = p + 64.0f * expf(scale_p[0] * ea[warp]) + bias_p[layer];
        s = (s >= 0.0f) ? s : 0.2f * s;
        g_s[warp] = s;
        atomicMaxFloat(&g_m[src], s);
    }
}

// exp(s - m[src]) and segment-sum denominator.
__global__ void k_expsum(const int* __restrict__ ei, int E) {
    int e = blockIdx.x * blockDim.x + threadIdx.x;
    if (e >= E) return;
    int src = ei[e];
    float ex = expf(g_s[e] - g_m[src]);
    g_s[e] = ex;
    atomicAdd(&g_den[src], ex);
}

// Scatter: next[dst] += alpha * cur[src]. Half-warp (16 lanes x float4) per edge.
__global__ void k_aggregate(const int* __restrict__ ei,
                            int curSel, const float* __restrict__ emb_in,
                            int nextSel, int E) {
    int gtid = blockIdx.x * blockDim.x + threadIdx.x;
    int e = gtid >> 4;          // half-warp id == edge id
    int l = gtid & 15;          // 16 float4 per 64-float row
    if (e >= E) return;
    const float* cur = sel_cur(curSel, emb_in);
    float* next = sel_next(nextSel);
    int src = ei[e];
    int dst = ei[E + e];
    float alpha = g_s[e] / (g_den[src] + 1e-16f);
    const float4* xp = (const float4*)(cur + (size_t)src * DIM);
    float4 x = xp[l];
    float4 v = make_float4(alpha * x.x, alpha * x.y, alpha * x.z, alpha * x.w);
    atomicAdd(((float4*)(next + (size_t)dst * DIM)) + l, v);
}

// acc += next
__global__ void k_accum(int nextSel, int nd) {
    int i = blockIdx.x * blockDim.x + threadIdx.x;
    if (i < nd) g_acc[i] += sel_next(nextSel)[i];
}

// out = (emb_in + acc) / 4
__global__ void k_final(const float* __restrict__ emb_in, float* __restrict__ out, int nd) {
    int i = blockIdx.x * blockDim.x + threadIdx.x;
    if (i < nd) out[i] = (emb_in[i] + g_acc[i]) * 0.25f;
}

extern "C" void kernel_launch(void* const* d_in, const int* in_sizes, int n_in,
                              void* d_out, int out_size) {
    const int*   ei    = (const int*)d_in[0];    // [2, E]
    const float* ea    = (const float*)d_in[1];  // [E]
    const float* emb   = (const float*)d_in[2];  // [N, 64]
    const float* W     = (const float*)d_in[3];  // [3, 64, 64]
    const float* bias  = (const float*)d_in[4];  // [3]
    const float* scale = (const float*)d_in[5];  // []

    int E  = in_sizes[1];
    int ND = in_sizes[2];
    int N  = ND / DIM;

    const int T = 256;
    int blk_nd   = (ND + T - 1) / T;
    int blk_e    = (E + T - 1) / T;
    int blk_e32  = (E * 32 + T - 1) / T;   // warp per edge
    int blk_e16  = (E * 16 + T - 1) / T;   // half-warp per edge

    k_zero_acc<<<blk_nd, T>>>(ND);

    // Layer buffer schedule: cur: emb -> A -> B ; next: A -> B -> A
    const int curSel[3]  = {0, 1, 2};
    const int nextSel[3] = {1, 2, 1};

    for (int l = 0; l < 3; l++) {
        k_layer_init<<<blk_nd, T>>>(nextSel[l], N);
        k_gemm64<<<(N + 3) / 4, T>>>(curSel[l], emb, W + (size_t)l * DIM * DIM, N);
        k_score<<<blk_e32, T>>>(ei, ea, curSel[l], emb, bias, scale, E, l);
        k_expsum<<<blk_e, T>>>(ei, E);
        k_aggregate<<<blk_e16, T>>>(ei, curSel[l], emb, nextSel[l], E);
        k_accum<<<blk_nd, T>>>(nextSel[l], ND);
    }

    float* out = (float*)d_out;
    bool two_outputs = (out_size >= 2 * ND);
    if (two_outputs) {
        // First output of the reference tuple is emb_table unchanged.
        cudaMemcpyAsync(out, emb, (size_t)ND * sizeof(float),
                        cudaMemcpyDeviceToDevice, 0);
        k_final<<<blk_nd, T>>>(emb, out + ND, ND);
    } else {
        k_final<<<blk_nd, T>>>(emb, out, ND);
    }
}

// round 3
// speedup vs baseline: 1.1490x; 1.1490x over previous
#include <cuda_runtime.h>
#include <cuda_bf16.h>

// Problem constants: N=150000 nodes, E=1e6 edges, D=64, 3 layers.
#define NMAX   150016
#define EMAX   1000448
#define DIM    64
#define SOFTEPS 1e-16f

// Scratch (no allocations allowed -> __device__ globals).
__device__ float g_Z[NMAX * DIM];       // emb @ W[l]
__device__ float g_bufA[NMAX * DIM];    // layer output ping
__device__ float g_bufB[NMAX * DIM];    // layer output pong
__device__ float g_acc[NMAX * DIM];     // running sum of layer outputs
__device__ float g_s[EMAX];             // per-edge score -> exp
__device__ float g_m[NMAX];             // segment max (by src)
__device__ float g_den[NMAX];           // segment sum of exp (by src)
// CSR-by-dst (built once per launch; edge_index is launch-constant)
__device__ int   g_cnt[NMAX];
__device__ int   g_rowstart[NMAX + 1];
__device__ int   g_cursor[NMAX];
__device__ int   g_perm[EMAX];
__device__ int   g_bsum[1024];

__device__ __forceinline__ const float* sel_cur(int sel, const float* emb_in) {
    if (sel == 0) return emb_in;
    return (sel == 1) ? g_bufA : g_bufB;
}
__device__ __forceinline__ float* sel_next(int sel) {
    return (sel == 1) ? g_bufA : g_bufB;
}

__device__ __forceinline__ void atomicMaxFloat(float* addr, float val) {
    if (val >= 0.0f) atomicMax((int*)addr, __float_as_int(val));
    else             atomicMin((unsigned int*)addr, __float_as_uint(val));
}

// ---------------- CSR build (once per launch) ----------------
__global__ void k_cnt_zero(int N) {
    int i = blockIdx.x * blockDim.x + threadIdx.x;
    if (i < N) g_cnt[i] = 0;
}
__global__ void k_hist(const int* __restrict__ ei, int E) {
    int e = blockIdx.x * blockDim.x + threadIdx.x;
    if (e < E) atomicAdd(&g_cnt[ei[E + e]], 1);   // dst
}
// per-256-block exclusive scan, block totals to g_bsum
__global__ void k_scan1(int N) {
    __shared__ int sh[256];
    int i = blockIdx.x * 256 + threadIdx.x;
    int v = (i < N) ? g_cnt[i] : 0;
    sh[threadIdx.x] = v;
    __syncthreads();
    for (int o = 1; o < 256; o <<= 1) {
        int t = (threadIdx.x >= o) ? sh[threadIdx.x - o] : 0;
        __syncthreads();
        sh[threadIdx.x] += t;
        __syncthreads();
    }
    if (i < N) g_rowstart[i] = sh[threadIdx.x] - v;  // pre-offset exclusive
    if (threadIdx.x == 255) g_bsum[blockIdx.x] = sh[255];
}
// single-block exclusive scan of block sums (nb <= 1024)
__global__ void k_scan2(int nb) {
    __shared__ int sh[1024];
    int t = threadIdx.x;
    int v = (t < nb) ? g_bsum[t] : 0;
    sh[t] = v;
    __syncthreads();
    for (int o = 1; o < 1024; o <<= 1) {
        int u = (t >= o) ? sh[t - o] : 0;
        __syncthreads();
        sh[t] += u;
        __syncthreads();
    }
    if (t < nb) g_bsum[t] = sh[t] - v;
}
__global__ void k_scan3(int N, int E) {
    int i = blockIdx.x * blockDim.x + threadIdx.x;
    if (i < N) {
        int rs = g_rowstart[i] + g_bsum[i >> 8];
        g_rowstart[i] = rs;
        g_cursor[i] = rs;
    }
    if (i == 0) g_rowstart[N] = E;
}
__global__ void k_scatter(const int* __restrict__ ei, int E) {
    int e = blockIdx.x * blockDim.x + threadIdx.x;
    if (e >= E) return;
    int pos = atomicAdd(&g_cursor[ei[E + e]], 1);
    g_perm[pos] = e;
}

// ---------------- per-layer kernels ----------------
__global__ void k_softmax_init(int N) {
    int i = blockIdx.x * blockDim.x + threadIdx.x;
    if (i < N) {
        g_m[i]   = __int_as_float(0xff800000);
        g_den[i] = 0.0f;
    }
}

// Z = cur @ W   (N x 64) @ (64 x 64). 4 rows per 256-thread block.
__global__ void k_gemm64(int curSel, const float* __restrict__ emb_in,
                         const float* __restrict__ W, int N) {
    __shared__ float sW[DIM * DIM];
    __shared__ float sX[4 * DIM];
    const float* X = sel_cur(curSel, emb_in);
    int tid = threadIdx.x;
    #pragma unroll
    for (int i = tid; i < DIM * DIM; i += 256) sW[i] = W[i];
    int r = tid >> 6, c = tid & 63;
    int row = blockIdx.x * 4 + r;
    sX[tid] = (row < N) ? X[row * DIM + c] : 0.0f;
    __syncthreads();
    float acc = 0.0f;
    #pragma unroll
    for (int k = 0; k < DIM; k++)
        acc = fmaf(sX[r * DIM + k], sW[k * DIM + c], acc);
    if (row < N) g_Z[row * DIM + c] = acc;
}

// Edge scores: 16 lanes (float4 each) per edge => 2 edges per warp.
__global__ void k_score(const int* __restrict__ ei, const float* __restrict__ ea,
                        int curSel, const float* __restrict__ emb_in,
                        const float* __restrict__ bias_p, const float* __restrict__ scale_p,
                        int E, int layer) {
    int t = blockIdx.x * blockDim.x + threadIdx.x;
    int e = t >> 4;
    int l = t & 15;
    if (e >= E) return;
    const float* cur = sel_cur(curSel, emb_in);
    int src = ei[e];
    int dst = ei[E + e];
    float4 z = ((const float4*)(g_Z + (size_t)dst * DIM))[l];
    float4 x = ((const float4*)(cur + (size_t)src * DIM))[l];
    float p = z.x * x.x + z.y * x.y + z.z * x.z + z.w * x.w;
    #pragma unroll
    for (int o = 8; o; o >>= 1) p += __shfl_xor_sync(0xffffffffu, p, o);
    if (l == 0) {
        float s = p + 64.0f * __expf(scale_p[0] * ea[e]) + bias_p[layer];
        s = (s >= 0.0f) ? s : 0.2f * s;
        g_s[e] = s;
        atomicMaxFloat(&g_m[src], s);
    }
}

// exp(s - m[src]) and segment-sum denominator.
__global__ void k_expsum(const int* __restrict__ ei, int E) {
    int e = blockIdx.x * blockDim.x + threadIdx.x;
    if (e >= E) return;
    int src = ei[e];
    float ex = __expf(g_s[e] - g_m[src]);
    g_s[e] = ex;
    atomicAdd(&g_den[src], ex);
}

// Gather-aggregate: one warp per dst node; no atomics, no pre-zero.
// Also folds acc accumulation (store on layer 0, add after).
__global__ void k_aggregate(const int* __restrict__ ei,
                            int curSel, const float* __restrict__ emb_in,
                            int nextSel, int N, int E, int layer) {
    int warp = (blockIdx.x * blockDim.x + threadIdx.x) >> 5;
    int lane = threadIdx.x & 31;
    if (warp >= N) return;
    const float* cur = sel_cur(curSel, emb_in);
    float* next = sel_next(nextSel);
    int beg = g_rowstart[warp];
    int end = g_rowstart[warp + 1];
    float ax = 0.0f, ay = 0.0f;
    int j = beg;
    for (; j + 2 <= end; j += 2) {
        int pe0 = g_perm[j], pe1 = g_perm[j + 1];
        int s0 = ei[pe0],    s1 = ei[pe1];
        float al0 = g_s[pe0] / (g_den[s0] + SOFTEPS);
        float al1 = g_s[pe1] / (g_den[s1] + SOFTEPS);
        float2 x0 = ((const float2*)(cur + (size_t)s0 * DIM))[lane];
        float2 x1 = ((const float2*)(cur + (size_t)s1 * DIM))[lane];
        ax = fmaf(al0, x0.x, fmaf(al1, x1.x, ax));
        ay = fmaf(al0, x0.y, fmaf(al1, x1.y, ay));
    }
    if (j < end) {
        int pe = g_perm[j];
        int s0 = ei[pe];
        float al = g_s[pe] / (g_den[s0] + SOFTEPS);
        float2 x0 = ((const float2*)(cur + (size_t)s0 * DIM))[lane];
        ax = fmaf(al, x0.x, ax);
        ay = fmaf(al, x0.y, ay);
    }
    float2 r = make_float2(ax, ay);
    ((float2*)(next + (size_t)warp * DIM))[lane] = r;
    float2* ap = ((float2*)(g_acc + (size_t)warp * DIM)) + lane;
    if (layer == 0) {
        *ap = r;
    } else {
        float2 a = *ap;
        a.x += ax; a.y += ay;
        *ap = a;
    }
}

// out = (emb_in + acc) / 4
__global__ void k_final(const float* __restrict__ emb_in, float* __restrict__ out, int nd) {
    int i = blockIdx.x * blockDim.x + threadIdx.x;
    if (i < nd) out[i] = (emb_in[i] + g_acc[i]) * 0.25f;
}

extern "C" void kernel_launch(void* const* d_in, const int* in_sizes, int n_in,
                              void* d_out, int out_size) {
    const int*   ei    = (const int*)d_in[0];    // [2, E]
    const float* ea    = (const float*)d_in[1];  // [E]
    const float* emb   = (const float*)d_in[2];  // [N, 64]
    const float* W     = (const float*)d_in[3];  // [3, 64, 64]
    const float* bias  = (const float*)d_in[4];  // [3]
    const float* scale = (const float*)d_in[5];  // []

    int E  = in_sizes[1];
    int ND = in_sizes[2];
    int N  = ND / DIM;

    const int T = 256;
    int blk_n   = (N + T - 1) / T;
    int blk_nd  = (ND + T - 1) / T;
    int blk_e   = (E + T - 1) / T;
    int blk_e16 = (E * 16 + T - 1) / T;   // 16 lanes per edge
    int blk_n32 = (N * 32 + T - 1) / T;   // warp per node

    // ---- CSR-by-dst build (edge_index is constant across the launch) ----
    k_cnt_zero<<<blk_n, T>>>(N);
    k_hist<<<blk_e, T>>>(ei, E);
    k_scan1<<<blk_n, 256>>>(N);
    k_scan2<<<1, 1024>>>(blk_n);
    k_scan3<<<blk_n, T>>>(N, E);
    k_scatter<<<blk_e, T>>>(ei, E);

    // Layer buffer schedule: cur: emb -> A -> B ; next: A -> B -> A
    const int curSel[3]  = {0, 1, 2};
    const int nextSel[3] = {1, 2, 1};

    for (int l = 0; l < 3; l++) {
        k_softmax_init<<<blk_n, T>>>(N);
        k_gemm64<<<(N + 3) / 4, T>>>(curSel[l], emb, W + (size_t)l * DIM * DIM, N);
        k_score<<<blk_e16, T>>>(ei, ea, curSel[l], emb, bias, scale, E, l);
        k_expsum<<<blk_e, T>>>(ei, E);
        k_aggregate<<<blk_n32, T>>>(ei, curSel[l], emb, nextSel[l], N, E, l);
    }

    float* out = (float*)d_out;
    if (out_size >= 2 * ND) {
        cudaMemcpyAsync(out, emb, (size_t)ND * sizeof(float),
                        cudaMemcpyDeviceToDevice, 0);
        k_final<<<blk_nd, T>>>(emb, out + ND, ND);
    } else {
        k_final<<<blk_nd, T>>>(emb, out, ND);
    }
}

// round 4
// speedup vs baseline: 1.2975x; 1.1293x over previous
#include <cuda_runtime.h>
#include <cuda_bf16.h>

// Problem constants: N=150000 nodes, E=1e6 edges, D=64, 3 layers.
#define NMAX   150016
#define EMAX   1000448
#define DIM    64
#define SOFTEPS 1e-16f
#define NEGINF __int_as_float(0xff800000)

// Scratch (no allocations allowed -> __device__ globals).
__device__ float g_Z[NMAX * DIM];
__device__ float g_bufA[NMAX * DIM];
__device__ float g_bufB[NMAX * DIM];
__device__ float g_acc[NMAX * DIM];
__device__ float g_s[EMAX];        // per-edge score
__device__ float g_alphaP[EMAX];   // alpha, stored in dst-CSR order
// dst-CSR: for the gather-aggregate
__device__ int g_cntD[NMAX], g_rsD[NMAX + 1], g_curD[NMAX];
__device__ int g_srcP[EMAX];       // src node of edge at dst-CSR slot
__device__ int g_posD[EMAX];       // e -> dst-CSR slot
// src-CSR: for the segment softmax
__device__ int g_cntS[NMAX], g_rsS[NMAX + 1], g_curS[NMAX];
__device__ int g_permS[EMAX];      // edge ids in src order
__device__ int g_bsumD[1024], g_bsumS[1024];

__device__ __forceinline__ const float* sel_cur(int sel, const float* emb_in) {
    if (sel == 0) return emb_in;
    return (sel == 1) ? g_bufA : g_bufB;
}
__device__ __forceinline__ float* sel_next(int sel) {
    return (sel == 1) ? g_bufA : g_bufB;
}
__device__ __forceinline__ int* csr_cnt(int w)  { return w ? g_cntS  : g_cntD; }
__device__ __forceinline__ int* csr_rs(int w)   { return w ? g_rsS   : g_rsD; }
__device__ __forceinline__ int* csr_cur(int w)  { return w ? g_curS  : g_curD; }
__device__ __forceinline__ int* csr_bsum(int w) { return w ? g_bsumS : g_bsumD; }

// ---------------- CSR build (once per launch) ----------------
__global__ void k_cnt_zero(int N) {
    int i = blockIdx.x * blockDim.x + threadIdx.x;
    if (i < N) { g_cntD[i] = 0; g_cntS[i] = 0; }
}
__global__ void k_hist(const int* __restrict__ ei, int E) {
    int e = blockIdx.x * blockDim.x + threadIdx.x;
    if (e < E) {
        atomicAdd(&g_cntD[ei[E + e]], 1);   // dst
        atomicAdd(&g_cntS[ei[e]], 1);       // src
    }
}
__global__ void k_scan1(int which, int N) {
    __shared__ int sh[256];
    int* cnt = csr_cnt(which);
    int* rs  = csr_rs(which);
    int i = blockIdx.x * 256 + threadIdx.x;
    int v = (i < N) ? cnt[i] : 0;
    sh[threadIdx.x] = v;
    __syncthreads();
    for (int o = 1; o < 256; o <<= 1) {
        int t = (threadIdx.x >= o) ? sh[threadIdx.x - o] : 0;
        __syncthreads();
        sh[threadIdx.x] += t;
        __syncthreads();
    }
    if (i < N) rs[i] = sh[threadIdx.x] - v;
    if (threadIdx.x == 255) csr_bsum(which)[blockIdx.x] = sh[255];
}
__global__ void k_scan2(int which, int nb) {
    __shared__ int sh[1024];
    int* bs = csr_bsum(which);
    int t = threadIdx.x;
    int v = (t < nb) ? bs[t] : 0;
    sh[t] = v;
    __syncthreads();
    for (int o = 1; o < 1024; o <<= 1) {
        int u = (t >= o) ? sh[t - o] : 0;
        __syncthreads();
        sh[t] += u;
        __syncthreads();
    }
    if (t < nb) bs[t] = sh[t] - v;
}
__global__ void k_scan3(int which, int N, int E) {
    int i = blockIdx.x * blockDim.x + threadIdx.x;
    int* rs = csr_rs(which);
    if (i < N) {
        int r = rs[i] + csr_bsum(which)[i >> 8];
        rs[i] = r;
        csr_cur(which)[i] = r;
    }
    if (i == 0) rs[N] = E;
}
__global__ void k_scatter(const int* __restrict__ ei, int E) {
    int e = blockIdx.x * blockDim.x + threadIdx.x;
    if (e >= E) return;
    int src = ei[e], dst = ei[E + e];
    int pd = atomicAdd(&g_curD[dst], 1);
    g_srcP[pd] = src;
    g_posD[e] = pd;
    int ps = atomicAdd(&g_curS[src], 1);
    g_permS[ps] = e;
}

// ---------------- per-layer kernels ----------------
// Z = cur @ W : 32 rows / 256-thread block, 8 outputs per thread.
__global__ void k_gemm64(int curSel, const float* __restrict__ emb_in,
                         const float* __restrict__ W, int N) {
    __shared__ float sW[DIM * DIM];        // 16 KB
    __shared__ float sX[32 * 65];          // padded rows, ~8.3 KB
    const float* X = sel_cur(curSel, emb_in);
    int tid = threadIdx.x;
    #pragma unroll
    for (int i = tid; i < DIM * DIM; i += 256) sW[i] = W[i];
    int rowBase = blockIdx.x * 32;
    #pragma unroll
    for (int i = tid; i < 32 * DIM; i += 256) {
        int r = i >> 6, c = i & 63;
        int row = rowBase + r;
        sX[r * 65 + c] = (row < N) ? X[(size_t)row * DIM + c] : 0.0f;
    }
    __syncthreads();
    int r  = tid >> 3;          // 0..31
    int cg = (tid & 7) * 8;     // column group
    float a0=0,a1=0,a2=0,a3=0,a4=0,a5=0,a6=0,a7=0;
    #pragma unroll
    for (int k = 0; k < DIM; k++) {
        float xv = sX[r * 65 + k];
        float4 w0 = *(const float4*)&sW[k * DIM + cg];
        float4 w1 = *(const float4*)&sW[k * DIM + cg + 4];
        a0 = fmaf(xv, w0.x, a0); a1 = fmaf(xv, w0.y, a1);
        a2 = fmaf(xv, w0.z, a2); a3 = fmaf(xv, w0.w, a3);
        a4 = fmaf(xv, w1.x, a4); a5 = fmaf(xv, w1.y, a5);
        a6 = fmaf(xv, w1.z, a6); a7 = fmaf(xv, w1.w, a7);
    }
    int row = rowBase + r;
    if (row < N) {
        float4* o = (float4*)&g_Z[(size_t)row * DIM + cg];
        o[0] = make_float4(a0, a1, a2, a3);
        o[1] = make_float4(a4, a5, a6, a7);
    }
}

// Edge scores: 16 lanes (float4) per edge. No atomics.
__global__ void k_score(const int* __restrict__ ei, const float* __restrict__ ea,
                        int curSel, const float* __restrict__ emb_in,
                        const float* __restrict__ bias_p, const float* __restrict__ scale_p,
                        int E, int layer) {
    int t = blockIdx.x * blockDim.x + threadIdx.x;
    int e = t >> 4;
    int l = t & 15;
    if (e >= E) return;
    const float* cur = sel_cur(curSel, emb_in);
    int src = ei[e];
    int dst = ei[E + e];
    float4 z = ((const float4*)(g_Z + (size_t)dst * DIM))[l];
    float4 x = ((const float4*)(cur + (size_t)src * DIM))[l];
    float p = z.x * x.x + z.y * x.y + z.z * x.z + z.w * x.w;
    #pragma unroll
    for (int o = 8; o; o >>= 1) p += __shfl_xor_sync(0xffffffffu, p, o);
    if (l == 0) {
        float s = p + 64.0f * __expf(scale_p[0] * ea[e]) + bias_p[layer];
        s = (s >= 0.0f) ? s : 0.2f * s;
        g_s[e] = s;
    }
}

// Segment softmax by src (no atomics): 8 lanes per node.
// Writes alpha straight into dst-CSR order via g_posD.
__global__ void k_softmax(int N) {
    int t = blockIdx.x * blockDim.x + threadIdx.x;
    int v = t >> 3;
    int l = t & 7;
    int beg = 0, end = 0;
    if (v < N) { beg = g_rsS[v]; end = g_rsS[v + 1]; }
    float m = NEGINF;
    for (int j = beg + l; j < end; j += 8)
        m = fmaxf(m, g_s[g_permS[j]]);
    #pragma unroll
    for (int o = 4; o; o >>= 1) m = fmaxf(m, __shfl_xor_sync(0xffffffffu, m, o));
    float den = 0.0f;
    for (int j = beg + l; j < end; j += 8)
        den += __expf(g_s[g_permS[j]] - m);
    #pragma unroll
    for (int o = 4; o; o >>= 1) den += __shfl_xor_sync(0xffffffffu, den, o);
    float inv = 1.0f / (den + SOFTEPS);
    for (int j = beg + l; j < end; j += 8) {
        int pe = g_permS[j];
        g_alphaP[g_posD[pe]] = __expf(g_s[pe] - m) * inv;
    }
}

// Gather-aggregate: warp per dst node. alphaP/srcP are sequential reads.
// layer<2: write next + update acc. layer==2: write final output directly.
__global__ void k_aggregate(int curSel, const float* __restrict__ emb_in,
                            int nextSel, float* __restrict__ out,
                            int N, int layer) {
    int warp = (blockIdx.x * blockDim.x + threadIdx.x) >> 5;
    int lane = threadIdx.x & 31;
    if (warp >= N) return;
    const float* cur = sel_cur(curSel, emb_in);
    int beg = g_rsD[warp];
    int end = g_rsD[warp + 1];
    float ax = 0.0f, ay = 0.0f;
    int j = beg;
    for (; j + 2 <= end; j += 2) {
        float al0 = g_alphaP[j];
        float al1 = g_alphaP[j + 1];
        int s0 = g_srcP[j];
        int s1 = g_srcP[j + 1];
        float2 x0 = ((const float2*)(cur + (size_t)s0 * DIM))[lane];
        float2 x1 = ((const float2*)(cur + (size_t)s1 * DIM))[lane];
        ax = fmaf(al0, x0.x, fmaf(al1, x1.x, ax));
        ay = fmaf(al0, x0.y, fmaf(al1, x1.y, ay));
    }
    if (j < end) {
        float al = g_alphaP[j];
        int s0 = g_srcP[j];
        float2 x0 = ((const float2*)(cur + (size_t)s0 * DIM))[lane];
        ax = fmaf(al, x0.x, ax);
        ay = fmaf(al, x0.y, ay);
    }
    size_t off = (size_t)warp * DIM;
    if (layer < 2) {
        ((float2*)(sel_next(nextSel) + off))[lane] = make_float2(ax, ay);
        float2* ap = ((float2*)(g_acc + off)) + lane;
        if (layer == 0) {
            *ap = make_float2(ax, ay);
        } else {
            float2 a = *ap;
            a.x += ax; a.y += ay;
            *ap = a;
        }
    } else {
        float2 a = ((const float2*)(g_acc + off))[lane];
        float2 e0 = ((const float2*)(emb_in + off))[lane];
        ((float2*)(out + off))[lane] =
            make_float2((e0.x + a.x + ax) * 0.25f, (e0.y + a.y + ay) * 0.25f);
    }
}

extern "C" void kernel_launch(void* const* d_in, const int* in_sizes, int n_in,
                              void* d_out, int out_size) {
    const int*   ei    = (const int*)d_in[0];
    const float* ea    = (const float*)d_in[1];
    const float* emb   = (const float*)d_in[2];
    const float* W     = (const float*)d_in[3];
    const float* bias  = (const float*)d_in[4];
    const float* scale = (const float*)d_in[5];

    int E  = in_sizes[1];
    int ND = in_sizes[2];
    int N  = ND / DIM;

    const int T = 256;
    int blk_n   = (N + T - 1) / T;
    int blk_e   = (E + T - 1) / T;
    int blk_e16 = (E * 16 + T - 1) / T;
    int blk_n8  = (N * 8  + T - 1) / T;
    int blk_n32 = (N * 32 + T - 1) / T;

    // ---- build both CSRs (edge_index is constant across the launch) ----
    k_cnt_zero<<<blk_n, T>>>(N);
    k_hist<<<blk_e, T>>>(ei, E);
    for (int w = 0; w < 2; w++) {
        k_scan1<<<blk_n, 256>>>(w, N);
        k_scan2<<<1, 1024>>>(w, blk_n);
        k_scan3<<<blk_n, T>>>(w, N, E);
    }
    k_scatter<<<blk_e, T>>>(ei, E);

    // Layer buffer schedule: cur: emb -> A -> B ; next: A -> B -> (none)
    const int curSel[3]  = {0, 1, 2};
    const int nextSel[3] = {1, 2, 1};

    float* out = (float*)d_out;
    float* out2 = out;
    if (out_size >= 2 * ND) {
        cudaMemcpyAsync(out, emb, (size_t)ND * sizeof(float),
                        cudaMemcpyDeviceToDevice, 0);
        out2 = out + ND;
    }

    for (int l = 0; l < 3; l++) {
        k_gemm64<<<(N + 31) / 32, T>>>(curSel[l], emb, W + (size_t)l * DIM * DIM, N);
        k_score<<<blk_e16, T>>>(ei, ea, curSel[l], emb, bias, scale, E, l);
        k_softmax<<<blk_n8, T>>>(N);
        k_aggregate<<<blk_n32, T>>>(curSel[l], emb, nextSel[l], out2, N, l);
    }
}

// round 7
// speedup vs baseline: 1.4831x; 1.1430x over previous
#include <cuda_runtime.h>
#include <cuda_bf16.h>

// Problem constants: N=150000 nodes, E=1e6 edges, D=64, 3 layers.
#define NMAX   150016
#define EMAX   1000448
#define DIM    64
#define SOFTEPS 1e-16f
#define NEGINF __int_as_float(0xff800000)

// Scratch (no allocations allowed -> __device__ globals).
__device__ float g_Z[NMAX * DIM];
__device__ float g_bufA[NMAX * DIM];
__device__ float g_bufB[NMAX * DIM];
__device__ float g_acc[NMAX * DIM];
__device__ float g_alphaP[EMAX];   // alpha, in dst-CSR order
// dst-CSR (gather-aggregate)
__device__ int g_cntD[NMAX], g_rsD[NMAX + 1], g_curD[NMAX];
__device__ int g_srcP[EMAX];       // src node at dst-CSR slot
// src-CSR (fused score+softmax)
__device__ int g_cntS[NMAX], g_rsS[NMAX + 1], g_curS[NMAX];
__device__ int   g_dstS[EMAX];     // dst node at src-CSR slot
__device__ int   g_posDS[EMAX];    // src-CSR slot -> dst-CSR slot
__device__ float g_eterm[EMAX];    // 64*exp(scale*ea[e]) at src-CSR slot
__device__ int g_bsumD[1024], g_bsumS[1024];

__device__ __forceinline__ const float* sel_cur(int sel, const float* emb_in) {
    if (sel == 0) return emb_in;
    return (sel == 1) ? g_bufA : g_bufB;
}
__device__ __forceinline__ float* sel_next(int sel) {
    return (sel == 1) ? g_bufA : g_bufB;
}
__device__ __forceinline__ int* csr_cnt(int w)  { return w ? g_cntS  : g_cntD; }
__device__ __forceinline__ int* csr_rs(int w)   { return w ? g_rsS   : g_rsD; }
__device__ __forceinline__ int* csr_cur(int w)  { return w ? g_curS  : g_curD; }
__device__ __forceinline__ int* csr_bsum(int w) { return w ? g_bsumS : g_bsumD; }

// ---------------- CSR build (once per launch) ----------------
__global__ void k_cnt_zero(int N) {
    int i = blockIdx.x * blockDim.x + threadIdx.x;
    if (i < N) { g_cntD[i] = 0; g_cntS[i] = 0; }
}
__global__ void k_hist(const int* __restrict__ ei, int E) {
    int e = blockIdx.x * blockDim.x + threadIdx.x;
    if (e < E) {
        atomicAdd(&g_cntD[ei[E + e]], 1);
        atomicAdd(&g_cntS[ei[e]], 1);
    }
}
__global__ void k_scan1(int which, int N) {
    __shared__ int sh[256];
    int* cnt = csr_cnt(which);
    int* rs  = csr_rs(which);
    int i = blockIdx.x * 256 + threadIdx.x;
    int v = (i < N) ? cnt[i] : 0;
    sh[threadIdx.x] = v;
    __syncthreads();
    for (int o = 1; o < 256; o <<= 1) {
        int t = (threadIdx.x >= o) ? sh[threadIdx.x - o] : 0;
        __syncthreads();
        sh[threadIdx.x] += t;
        __syncthreads();
    }
    if (i < N) rs[i] = sh[threadIdx.x] - v;
    if (threadIdx.x == 255) csr_bsum(which)[blockIdx.x] = sh[255];
}
__global__ void k_scan2(int which, int nb) {
    __shared__ int sh[1024];
    int* bs = csr_bsum(which);
    int t = threadIdx.x;
    int v = (t < nb) ? bs[t] : 0;
    sh[t] = v;
    __syncthreads();
    for (int o = 1; o < 1024; o <<= 1) {
        int u = (t >= o) ? sh[t - o] : 0;
        __syncthreads();
        sh[t] += u;
        __syncthreads();
    }
    if (t < nb) bs[t] = sh[t] - v;
}
__global__ void k_scan3(int which, int N, int E) {
    int i = blockIdx.x * blockDim.x + threadIdx.x;
    int* rs = csr_rs(which);
    if (i < N) {
        int r = rs[i] + csr_bsum(which)[i >> 8];
        rs[i] = r;
        csr_cur(which)[i] = r;
    }
    if (i == 0) rs[N] = E;
}
__global__ void k_scatter(const int* __restrict__ ei, const float* __restrict__ ea,
                          const float* __restrict__ scale_p, int E) {
    int e = blockIdx.x * blockDim.x + threadIdx.x;
    if (e >= E) return;
    int src = ei[e], dst = ei[E + e];
    int pd = atomicAdd(&g_curD[dst], 1);
    g_srcP[pd] = src;
    int ps = atomicAdd(&g_curS[src], 1);
    g_dstS[ps]  = dst;
    g_posDS[ps] = pd;
    g_eterm[ps] = 64.0f * __expf(scale_p[0] * ea[e]);
}

// ---------------- per-layer kernels ----------------
// Z = cur @ W : 32 rows / 256-thread block, 8 outputs per thread.
__global__ void k_gemm64(int curSel, const float* __restrict__ emb_in,
                         const float* __restrict__ W, int N) {
    __shared__ float sW[DIM * DIM];
    __shared__ float sX[32 * 65];
    const float* X = sel_cur(curSel, emb_in);
    int tid = threadIdx.x;
    #pragma unroll
    for (int i = tid; i < DIM * DIM; i += 256) sW[i] = W[i];
    int rowBase = blockIdx.x * 32;
    #pragma unroll
    for (int i = tid; i < 32 * DIM; i += 256) {
        int r = i >> 6, c = i & 63;
        int row = rowBase + r;
        sX[r * 65 + c] = (row < N) ? X[(size_t)row * DIM + c] : 0.0f;
    }
    __syncthreads();
    int r  = tid >> 3;
    int cg = (tid & 7) * 8;
    float a0=0,a1=0,a2=0,a3=0,a4=0,a5=0,a6=0,a7=0;
    #pragma unroll
    for (int k = 0; k < DIM; k++) {
        float xv = sX[r * 65 + k];
        float4 w0 = *(const float4*)&sW[k * DIM + cg];
        float4 w1 = *(const float4*)&sW[k * DIM + cg + 4];
        a0 = fmaf(xv, w0.x, a0); a1 = fmaf(xv, w0.y, a1);
        a2 = fmaf(xv, w0.z, a2); a3 = fmaf(xv, w0.w, a3);
        a4 = fmaf(xv, w1.x, a4); a5 = fmaf(xv, w1.y, a5);
        a6 = fmaf(xv, w1.z, a6); a7 = fmaf(xv, w1.w, a7);
    }
    int row = rowBase + r;
    if (row < N) {
        float4* o = (float4*)&g_Z[(size_t)row * DIM + cg];
        o[0] = make_float4(a0, a1, a2, a3);
        o[1] = make_float4(a4, a5, a6, a7);
    }
}

// Fused edge-score + segment-softmax: one warp per src node.
// x = cur[v] held in registers (each 16-lane half holds the full row as float4).
// 2 edges in flight per warp iteration (one per half).
// NOTE: all width-16 shuffles inside deg-dependent loops use the HALF mask —
// halves can have different trip counts (odd deg), so a full mask deadlocks.
__global__ void k_score_softmax(int curSel, const float* __restrict__ emb_in,
                                const float* __restrict__ bias_p, int N, int layer) {
    __shared__ float ssc[8][32];            // 8 warps/block
    int gt   = blockIdx.x * blockDim.x + threadIdx.x;
    int v    = gt >> 5;
    int lane = threadIdx.x & 31;
    int wid  = threadIdx.x >> 5;
    if (v >= N) return;
    int beg = g_rsS[v], end = g_rsS[v + 1];
    int deg = end - beg;
    if (deg == 0) return;
    const float* cur = sel_cur(curSel, emb_in);
    int half = lane >> 4;                   // 0/1: which edge of the pair
    int hl   = lane & 15;                   // lane within half
    unsigned hmask = 0xFFFFu << (half << 4);
    float4 x = ((const float4*)(cur + (size_t)v * DIM))[hl];
    float bias = bias_p[layer];

    if (deg <= 32) {
        for (int t2 = half; t2 < deg; t2 += 2) {
            int j = beg + t2;
            int dst = g_dstS[j];
            float4 z = ((const float4*)(g_Z + (size_t)dst * DIM))[hl];
            float p = z.x * x.x + z.y * x.y + z.z * x.z + z.w * x.w;
            #pragma unroll
            for (int o = 8; o; o >>= 1)
                p += __shfl_xor_sync(hmask, p, o, 16);
            float s = p + g_eterm[j] + bias;
            s = (s >= 0.0f) ? s : 0.2f * s;
            if (hl == 0) ssc[wid][t2] = s;
        }
        __syncwarp();
        float sv = (lane < deg) ? ssc[wid][lane] : NEGINF;
        float m = sv;
        #pragma unroll
        for (int o = 16; o; o >>= 1)
            m = fmaxf(m, __shfl_xor_sync(0xffffffffu, m, o));
        float ex = (lane < deg) ? __expf(sv - m) : 0.0f;
        float den = ex;
        #pragma unroll
        for (int o = 16; o; o >>= 1)
            den += __shfl_xor_sync(0xffffffffu, den, o);
        if (lane < deg)
            g_alphaP[g_posDS[beg + lane]] = ex / (den + SOFTEPS);
    } else {
        // Rare fallback (deg>32): 3 passes, recompute.
        float mloc = NEGINF;
        for (int t2 = half; t2 < deg; t2 += 2) {
            int j = beg + t2;
            int dst = g_dstS[j];
            float4 z = ((const float4*)(g_Z + (size_t)dst * DIM))[hl];
            float p = z.x * x.x + z.y * x.y + z.z * x.z + z.w * x.w;
            #pragma unroll
            for (int o = 8; o; o >>= 1)
                p += __shfl_xor_sync(hmask, p, o, 16);
            float s = p + g_eterm[j] + bias;
            s = (s >= 0.0f) ? s : 0.2f * s;
            mloc = fmaxf(mloc, s);
        }
        #pragma unroll
        for (int o = 16; o; o >>= 1)
            mloc = fmaxf(mloc, __shfl_xor_sync(0xffffffffu, mloc, o));
        float dloc = 0.0f;
        for (int t2 = half; t2 < deg; t2 += 2) {
            int j = beg + t2;
            int dst = g_dstS[j];
            float4 z = ((const float4*)(g_Z + (size_t)dst * DIM))[hl];
            float p = z.x * x.x + z.y * x.y + z.z * x.z + z.w * x.w;
            #pragma unroll
            for (int o = 8; o; o >>= 1)
                p += __shfl_xor_sync(hmask, p, o, 16);
            float s = p + g_eterm[j] + bias;
            s = (s >= 0.0f) ? s : 0.2f * s;
            dloc += __expf(s - mloc);       // identical on all 16 lanes of half
        }
        #pragma unroll
        for (int o = 16; o; o >>= 1)
            dloc += __shfl_xor_sync(0xffffffffu, dloc, o);
        float den = dloc * 0.0625f;         // /16 (each edge counted by 16 lanes)
        float inv = 1.0f / (den + SOFTEPS);
        for (int t2 = half; t2 < deg; t2 += 2) {
            int j = beg + t2;
            int dst = g_dstS[j];
            float4 z = ((const float4*)(g_Z + (size_t)dst * DIM))[hl];
            float p = z.x * x.x + z.y * x.y + z.z * x.z + z.w * x.w;
            #pragma unroll
            for (int o = 8; o; o >>= 1)
                p += __shfl_xor_sync(hmask, p, o, 16);
            float s = p + g_eterm[j] + bias;
            s = (s >= 0.0f) ? s : 0.2f * s;
            if (hl == 0)
                g_alphaP[g_posDS[j]] = __expf(s - mloc) * inv;
        }
    }
}

// Gather-aggregate: warp per dst node; alphaP/srcP sequential, 4x unroll.
__global__ void k_aggregate(int curSel, const float* __restrict__ emb_in,
                            int nextSel, float* __restrict__ out,
                            int N, int layer) {
    int warp = (blockIdx.x * blockDim.x + threadIdx.x) >> 5;
    int lane = threadIdx.x & 31;
    if (warp >= N) return;
    const float* cur = sel_cur(curSel, emb_in);
    int beg = g_rsD[warp];
    int end = g_rsD[warp + 1];
    float ax = 0.0f, ay = 0.0f;
    int j = beg;
    for (; j + 4 <= end; j += 4) {
        float al0 = g_alphaP[j],     al1 = g_alphaP[j + 1];
        float al2 = g_alphaP[j + 2], al3 = g_alphaP[j + 3];
        int s0 = g_srcP[j],     s1 = g_srcP[j + 1];
        int s2 = g_srcP[j + 2], s3 = g_srcP[j + 3];
        float2 x0 = ((const float2*)(cur + (size_t)s0 * DIM))[lane];
        float2 x1 = ((const float2*)(cur + (size_t)s1 * DIM))[lane];
        float2 x2 = ((const float2*)(cur + (size_t)s2 * DIM))[lane];
        float2 x3 = ((const float2*)(cur + (size_t)s3 * DIM))[lane];
        ax = fmaf(al0, x0.x, fmaf(al1, x1.x, fmaf(al2, x2.x, fmaf(al3, x3.x, ax))));
        ay = fmaf(al0, x0.y, fmaf(al1, x1.y, fmaf(al2, x2.y, fmaf(al3, x3.y, ay))));
    }
    for (; j < end; j++) {
        float al = g_alphaP[j];
        int s0 = g_srcP[j];
        float2 x0 = ((const float2*)(cur + (size_t)s0 * DIM))[lane];
        ax = fmaf(al, x0.x, ax);
        ay = fmaf(al, x0.y, ay);
    }
    size_t off = (size_t)warp * DIM;
    if (layer < 2) {
        ((float2*)(sel_next(nextSel) + off))[lane] = make_float2(ax, ay);
        float2* ap = ((float2*)(g_acc + off)) + lane;
        if (layer == 0) {
            *ap = make_float2(ax, ay);
        } else {
            float2 a = *ap;
            a.x += ax; a.y += ay;
            *ap = a;
        }
    } else {
        float2 a = ((const float2*)(g_acc + off))[lane];
        float2 e0 = ((const float2*)(emb_in + off))[lane];
        ((float2*)(out + off))[lane] =
            make_float2((e0.x + a.x + ax) * 0.25f, (e0.y + a.y + ay) * 0.25f);
    }
}

extern "C" void kernel_launch(void* const* d_in, const int* in_sizes, int n_in,
                              void* d_out, int out_size) {
    const int*   ei    = (const int*)d_in[0];
    const float* ea    = (const float*)d_in[1];
    const float* emb   = (const float*)d_in[2];
    const float* W     = (const float*)d_in[3];
    const float* bias  = (const float*)d_in[4];
    const float* scale = (const float*)d_in[5];

    int E  = in_sizes[1];
    int ND = in_sizes[2];
    int N  = ND / DIM;

    const int T = 256;
    int blk_n   = (N + T - 1) / T;
    int blk_e   = (E + T - 1) / T;
    int blk_n32 = (N * 32 + T - 1) / T;

    // ---- build both CSRs (edge_index is constant across the launch) ----
    k_cnt_zero<<<blk_n, T>>>(N);
    k_hist<<<blk_e, T>>>(ei, E);
    for (int w = 0; w < 2; w++) {
        k_scan1<<<blk_n, 256>>>(w, N);
        k_scan2<<<1, 1024>>>(w, blk_n);
        k_scan3<<<blk_n, T>>>(w, N, E);
    }
    k_scatter<<<blk_e, T>>>(ei, ea, scale, E);

    const int curSel[3]  = {0, 1, 2};
    const int nextSel[3] = {1, 2, 1};

    float* out = (float*)d_out;
    float* out2 = out;
    if (out_size >= 2 * ND) {
        cudaMemcpyAsync(out, emb, (size_t)ND * sizeof(float),
                        cudaMemcpyDeviceToDevice, 0);
        out2 = out + ND;
    }

    for (int l = 0; l < 3; l++) {
        k_gemm64<<<(N + 31) / 32, T>>>(curSel[l], emb, W + (size_t)l * DIM * DIM, N);
        k_score_softmax<<<blk_n32, T>>>(curSel[l], emb, bias, N, l);
        k_aggregate<<<blk_n32, T>>>(curSel[l], emb, nextSel[l], out2, N, l);
    }
}